// round 11
// baseline (speedup 1.0000x reference)
#include <cuda_runtime.h>
#include <cuda_bf16.h>
#include <cuda_fp16.h>
#include <math.h>

#define NN 100000
#define NE 1600000
#define NG 512
#define FA 40
#define FB 80
#define FC 128
#define FH 512   // fc1 hidden

typedef unsigned long long ULL;

// ---------------- f32x2 helpers (Blackwell dual-FP32 pipe) ----------------
__device__ __forceinline__ void fma2(ULL &d, ULL a, ULL b) {
    asm("fma.rn.f32x2 %0, %1, %2, %0;" : "+l"(d) : "l"(a), "l"(b));
}
__device__ __forceinline__ ULL bcast2(float x) {
    ULL r; asm("mov.b64 %0, {%1, %1};" : "=l"(r) : "f"(x)); return r;
}
__device__ __forceinline__ float2 upk2(ULL v) {
    float2 f; asm("mov.b64 {%0, %1}, %2;" : "=f"(f.x), "=f"(f.y) : "l"(v)); return f;
}

// ---------------- static device scratch ----------------
__device__ float  g_dinv[NN];       // deg -> rsqrt(deg)
__device__ float  g_self[NN];       // dinv^2 (self-loop norm)
__device__ int    g_cnt[NN];
__device__ int    g_fill[NN];
__device__ int    g_rowptr[NN + 1];
__device__ int    g_bsum[128];
__device__ int    g_gstart[NG + 1];
__device__ ULL    g_epack[NE];      // low32 = src id, high32 = norm (float bits)
__device__ __half g_G1h[NN * FA];   // G1 = X @ W1 in fp16 (layer-1 gather operand)
__device__ __half g_H1h[NN * FA];   // H1 in fp16
__device__ __half g_H2h[NN * FB];   // H2 in fp16
__device__ float  g_H3[NN * FC];    // H3 fp32 (pool input)
__device__ float  g_T[NN * FB];     // aggregated features (GEMM input, fp32)
__device__ float  g_pool[NG * FC];
__device__ float  g_fc1[NG * FH];

// ---------------- init ----------------
__global__ void k_init() {
    int i = blockIdx.x * blockDim.x + threadIdx.x;
    if (i >= NN) return;
    g_dinv[i] = 1.0f; g_cnt[i] = 0; g_fill[i] = 0;
}

// ---------------- graph segment boundaries (batch sorted) ----------------
__global__ void k_gbounds(const int* __restrict__ batch) {
    int i = blockIdx.x * blockDim.x + threadIdx.x;
    if (i >= NN) return;
    int b = batch[i];
    if (i == 0) {
        for (int g = 0; g <= b; g++) g_gstart[g] = 0;
    } else {
        int p = batch[i - 1];
        for (int g = p + 1; g <= b; g++) g_gstart[g] = i;
    }
    if (i == NN - 1) {
        for (int g = b + 1; g <= NG; g++) g_gstart[g] = NN;
    }
}

// ---------------- degree + count (fire-and-forget -> REDG) ----------------
__global__ void k_deg(const int* __restrict__ ei, const float* __restrict__ ew) {
    int e = blockIdx.x * blockDim.x + threadIdx.x;
    if (e >= NE) return;
    int c = ei[NE + e];
    atomicAdd(&g_dinv[c], ew[e]);
    atomicAdd(&g_cnt[c], 1);
}

// ---------------- scan phase 1: block sums (+ dinv transform folded) ----------------
__global__ void k_scan1() {
    __shared__ int sh[1024];
    int i = blockIdx.x * 1024 + threadIdx.x;
    if (i < NN) {
        float r = rsqrtf(g_dinv[i]);   // deg >= 1 (self loop)
        g_dinv[i] = r;
        g_self[i] = r * r;
    }
    sh[threadIdx.x] = (i < NN) ? g_cnt[i] : 0;
    __syncthreads();
    for (int s = 512; s > 0; s >>= 1) {
        if (threadIdx.x < s) sh[threadIdx.x] += sh[threadIdx.x + s];
        __syncthreads();
    }
    if (threadIdx.x == 0) g_bsum[blockIdx.x] = sh[0];
}

// ---------------- scan phase 2: intra-block scan + inline lookback ----------------
__global__ void k_scan3() {
    __shared__ int sh[1024];
    __shared__ int pre[128];
    int tid = threadIdx.x;
    int i = blockIdx.x * 1024 + tid;
    int v = (i < NN) ? g_cnt[i] : 0;
    sh[tid] = v;
    if (tid < 128) pre[tid] = (tid < blockIdx.x) ? g_bsum[tid] : 0;
    __syncthreads();
    for (int off = 1; off < 1024; off <<= 1) {
        int t = (tid >= off) ? sh[tid - off] : 0;
        __syncthreads();
        sh[tid] += t;
        __syncthreads();
    }
    if (tid < 64) pre[tid] += pre[tid + 64];
    __syncthreads();
    if (tid < 32) {
        int p = pre[tid] + pre[tid + 32];
#pragma unroll
        for (int off = 16; off > 0; off >>= 1)
            p += __shfl_down_sync(0xFFFFFFFFu, p, off);
        if (tid == 0) pre[0] = p;
    }
    __syncthreads();
    if (i <= NN) g_rowptr[i] = pre[0] + sh[tid] - v;
}

// ---------------- edge fill (CSR by destination, packed meta) ----------------
__global__ void k_fill(const int* __restrict__ ei, const float* __restrict__ ew) {
    int e = blockIdx.x * blockDim.x + threadIdx.x;
    if (e >= NE) return;
    int r = ei[e];
    int c = ei[NE + e];
    int pos = g_rowptr[c] + atomicAdd(&g_fill[c], 1);
    float norm = g_dinv[r] * ew[e] * g_dinv[c];
    g_epack[pos] = (ULL)(unsigned)r | ((ULL)__float_as_uint(norm) << 32);
}

// ---------------- gather-aggregate (warp per dst node), fp16 input ----------------
// EPI=0: OUT(float) = Â H.   EPI=1: OUT(half) = relu(Â H + bias)
template<int F, int EPI>
__global__ void k_agg(const __half* __restrict__ H, const float* __restrict__ bias,
                      void* __restrict__ OUT) {
    int warp = threadIdx.x >> 5;
    int lane = threadIdx.x & 31;
    int n = blockIdx.x * (blockDim.x >> 5) + warp;
    if (n >= NN) return;
    constexpr int NH = F / 2;            // half2 per row: 20 / 40
    constexpr int J  = (NH + 31) / 32;   // 1 / 2
    float2 acc[J];
    float sn = g_self[n];
    const __half2* hn = (const __half2*)(H + (size_t)n * F);
#pragma unroll
    for (int j = 0; j < J; j++) {
        int c = lane + 32 * j;
        acc[j] = make_float2(0.f, 0.f);
        if (c < NH) {
            float2 v = __half22float2(hn[c]);
            acc[j].x = sn * v.x; acc[j].y = sn * v.y;
        }
    }
    int beg = g_rowptr[n], end = g_rowptr[n + 1];
    int e = beg;
    for (; e + 4 <= end; e += 4) {
        ULL m0 = g_epack[e],     m1 = g_epack[e + 1];
        ULL m2 = g_epack[e + 2], m3 = g_epack[e + 3];
        const __half2* h0 = (const __half2*)(H + (size_t)(unsigned)(m0 & 0xFFFFFFFFu) * F);
        const __half2* h1 = (const __half2*)(H + (size_t)(unsigned)(m1 & 0xFFFFFFFFu) * F);
        const __half2* h2 = (const __half2*)(H + (size_t)(unsigned)(m2 & 0xFFFFFFFFu) * F);
        const __half2* h3 = (const __half2*)(H + (size_t)(unsigned)(m3 & 0xFFFFFFFFu) * F);
        float w0 = __uint_as_float((unsigned)(m0 >> 32));
        float w1 = __uint_as_float((unsigned)(m1 >> 32));
        float w2 = __uint_as_float((unsigned)(m2 >> 32));
        float w3 = __uint_as_float((unsigned)(m3 >> 32));
#pragma unroll
        for (int j = 0; j < J; j++) {
            int c = lane + 32 * j;
            if (c < NH) {
                float2 v0 = __half22float2(h0[c]);
                float2 v1 = __half22float2(h1[c]);
                float2 v2 = __half22float2(h2[c]);
                float2 v3 = __half22float2(h3[c]);
                acc[j].x += w0 * v0.x + w1 * v1.x + w2 * v2.x + w3 * v3.x;
                acc[j].y += w0 * v0.y + w1 * v1.y + w2 * v2.y + w3 * v3.y;
            }
        }
    }
    for (; e < end; e++) {
        ULL m = g_epack[e];
        const __half2* hp = (const __half2*)(H + (size_t)(unsigned)(m & 0xFFFFFFFFu) * F);
        float wn = __uint_as_float((unsigned)(m >> 32));
#pragma unroll
        for (int j = 0; j < J; j++) {
            int c = lane + 32 * j;
            if (c < NH) {
                float2 v = __half22float2(hp[c]);
                acc[j].x += wn * v.x;
                acc[j].y += wn * v.y;
            }
        }
    }
#pragma unroll
    for (int j = 0; j < J; j++) {
        int c = lane + 32 * j;
        if (c < NH) {
            if (EPI) {
                float bx = bias[2 * c], by = bias[2 * c + 1];
                __half2* op = (__half2*)((__half*)OUT + (size_t)n * F);
                op[c] = __floats2half2_rn(fmaxf(acc[j].x + bx, 0.f),
                                          fmaxf(acc[j].y + by, 0.f));
            } else {
                float2* op = (float2*)((float*)OUT + (size_t)n * F);
                op[c] = acc[j];
            }
        }
    }
}

// ---------------- f32x2 SGEMM: C = A @ W (+bias,+relu per EPI), fp32/fp16 out ----------------
template<int BM, int BN, int OUTH, int EPI>
__global__ void k_gemmF(const float* __restrict__ A, const float* __restrict__ W,
                        const float* __restrict__ bias, void* __restrict__ C,
                        int N, int K, int M) {
    constexpr int BK = 8;
    constexpr int NT = (BM / 8) * (BN / 8);
    __shared__ __align__(16) float As[BK][BM];
    __shared__ __align__(16) float Ws[BK][BN];
    int tid = threadIdx.x;
    int tx = tid % (BN / 8);
    int ty = tid / (BN / 8);
    int rowBase = blockIdx.x * BM;
    int colBase = blockIdx.y * BN;

    ULL acc[8][4];
#pragma unroll
    for (int i = 0; i < 8; i++)
#pragma unroll
        for (int j = 0; j < 4; j++) acc[i][j] = 0ull;

    for (int kt = 0; kt < K; kt += BK) {
        for (int idx = tid; idx < BM * BK / 4; idx += NT) {
            int r = idx % BM;
            int kp = (idx / BM) * 4;
            int gr = rowBase + r;
            float4 v = make_float4(0.f, 0.f, 0.f, 0.f);
            if (gr < N) v = *(const float4*)(A + (size_t)gr * K + kt + kp);
            As[kp + 0][r] = v.x; As[kp + 1][r] = v.y;
            As[kp + 2][r] = v.z; As[kp + 3][r] = v.w;
        }
        for (int idx = tid; idx < BK * BN / 4; idx += NT) {
            int kk = idx / (BN / 4);
            int j = (idx % (BN / 4)) * 4;
            *(float4*)&Ws[kk][j] = *(const float4*)(W + (size_t)(kt + kk) * M + colBase + j);
        }
        __syncthreads();
#pragma unroll
        for (int kk = 0; kk < BK; kk++) {
            float4 a0 = *(float4*)&As[kk][ty * 4];
            float4 a1 = *(float4*)&As[kk][BM / 2 + ty * 4];
            ulonglong2 w01 = *(ulonglong2*)&Ws[kk][tx * 4];
            ulonglong2 w23 = *(ulonglong2*)&Ws[kk][BN / 2 + tx * 4];
            float av[8] = {a0.x, a0.y, a0.z, a0.w, a1.x, a1.y, a1.z, a1.w};
#pragma unroll
            for (int i = 0; i < 8; i++) {
                ULL ap = bcast2(av[i]);
                fma2(acc[i][0], ap, w01.x);
                fma2(acc[i][1], ap, w01.y);
                fma2(acc[i][2], ap, w23.x);
                fma2(acc[i][3], ap, w23.y);
            }
        }
        __syncthreads();
    }

    int c0 = colBase + tx * 4;
    int c1 = colBase + BN / 2 + tx * 4;
    float b0x = 0.f, b0y = 0.f, b0z = 0.f, b0w = 0.f;
    float b1x = 0.f, b1y = 0.f, b1z = 0.f, b1w = 0.f;
    if (EPI) {
        b0x = bias[c0]; b0y = bias[c0 + 1]; b0z = bias[c0 + 2]; b0w = bias[c0 + 3];
        b1x = bias[c1]; b1y = bias[c1 + 1]; b1z = bias[c1 + 2]; b1w = bias[c1 + 3];
    }
#pragma unroll
    for (int i = 0; i < 8; i++) {
        int gr = rowBase + ((i < 4) ? (ty * 4 + i) : (BM / 2 + ty * 4 + (i - 4)));
        if (gr >= N) continue;
        float2 p;
        float v0, v1, v2, v3, v4, v5, v6, v7;
        p = upk2(acc[i][0]); v0 = p.x + b0x; v1 = p.y + b0y;
        p = upk2(acc[i][1]); v2 = p.x + b0z; v3 = p.y + b0w;
        p = upk2(acc[i][2]); v4 = p.x + b1x; v5 = p.y + b1y;
        p = upk2(acc[i][3]); v6 = p.x + b1z; v7 = p.y + b1w;
        if (EPI) {
            v0 = fmaxf(v0, 0.f); v1 = fmaxf(v1, 0.f); v2 = fmaxf(v2, 0.f); v3 = fmaxf(v3, 0.f);
            v4 = fmaxf(v4, 0.f); v5 = fmaxf(v5, 0.f); v6 = fmaxf(v6, 0.f); v7 = fmaxf(v7, 0.f);
        }
        if (OUTH) {
            __half* cp = (__half*)C + (size_t)gr * M;
            *(__half2*)(cp + c0)     = __floats2half2_rn(v0, v1);
            *(__half2*)(cp + c0 + 2) = __floats2half2_rn(v2, v3);
            *(__half2*)(cp + c1)     = __floats2half2_rn(v4, v5);
            *(__half2*)(cp + c1 + 2) = __floats2half2_rn(v6, v7);
        } else {
            float* cp = (float*)C + (size_t)gr * M;
            *(float2*)(cp + c0)     = make_float2(v0, v1);
            *(float2*)(cp + c0 + 2) = make_float2(v2, v3);
            *(float2*)(cp + c1)     = make_float2(v4, v5);
            *(float2*)(cp + c1 + 2) = make_float2(v6, v7);
        }
    }
}

// ---------------- segmented global max pool (4 row-parallel lanes) ----------------
__global__ void k_pool(const float* __restrict__ H3) {
    __shared__ float red[4][FC];
    int g = blockIdx.x;
    int c = threadIdx.x;
    int ry = threadIdx.y;
    int beg = g_gstart[g], end = g_gstart[g + 1];
    float m = 0.f;                // H3 is post-relu (>= 0)
    for (int n = beg + ry; n < end; n += 4)
        m = fmaxf(m, H3[(size_t)n * FC + c]);
    red[ry][c] = m;
    __syncthreads();
    if (ry == 0) {
        m = fmaxf(fmaxf(red[0][c], red[1][c]), fmaxf(red[2][c], red[3][c]));
        g_pool[g * FC + c] = m;
    }
}

// ---------------- fc2 + softmax ----------------
__global__ void k_fc2(const float* __restrict__ Wfc2, const float* __restrict__ bfc2,
                      float* __restrict__ out) {
    int warp = threadIdx.x >> 5;
    int lane = threadIdx.x & 31;
    int g = blockIdx.x * (blockDim.x >> 5) + warp;
    if (g >= NG) return;
    float s0 = 0.f, s1 = 0.f;
    for (int k = lane; k < FH; k += 32) {
        float v = g_fc1[g * FH + k];
        s0 += v * Wfc2[k * 2 + 0];
        s1 += v * Wfc2[k * 2 + 1];
    }
#pragma unroll
    for (int off = 16; off > 0; off >>= 1) {
        s0 += __shfl_down_sync(0xFFFFFFFFu, s0, off);
        s1 += __shfl_down_sync(0xFFFFFFFFu, s1, off);
    }
    if (lane == 0) {
        s0 += bfc2[0]; s1 += bfc2[1];
        float m = fmaxf(s0, s1);
        float e0 = expf(s0 - m), e1 = expf(s1 - m);
        float inv = 1.f / (e0 + e1);
        out[g * 2 + 0] = e0 * inv;
        out[g * 2 + 1] = e1 * inv;
    }
}

// ---------------- host launch ----------------
extern "C" void kernel_launch(void* const* d_in, const int* in_sizes, int n_in,
                              void* d_out, int out_size) {
    const float* x     = (const float*)d_in[0];
    const int*   ei    = (const int*)  d_in[1];
    const float* ew    = (const float*)d_in[2];
    const int*   batch = (const int*)  d_in[3];
    const float* W1    = (const float*)d_in[4];
    const float* b1    = (const float*)d_in[5];
    const float* W2    = (const float*)d_in[6];
    const float* b2    = (const float*)d_in[7];
    const float* W3    = (const float*)d_in[8];
    const float* b3    = (const float*)d_in[9];
    const float* Wfc1  = (const float*)d_in[10];
    const float* bfc1  = (const float*)d_in[11];
    const float* Wfc2  = (const float*)d_in[12];
    const float* bfc2  = (const float*)d_in[13];
    float* out = (float*)d_out;

    __half *pG1h, *pH1h, *pH2h;
    float *pH3, *pT, *pPool, *pFc1;
    cudaGetSymbolAddress((void**)&pG1h,  g_G1h);
    cudaGetSymbolAddress((void**)&pH1h,  g_H1h);
    cudaGetSymbolAddress((void**)&pH2h,  g_H2h);
    cudaGetSymbolAddress((void**)&pH3,   g_H3);
    cudaGetSymbolAddress((void**)&pT,    g_T);
    cudaGetSymbolAddress((void**)&pPool, g_pool);
    cudaGetSymbolAddress((void**)&pFc1,  g_fc1);

    int nblkN  = (NN + 255) / 256;
    int nblkE  = (NE + 255) / 256;
    int nblkSc = (NN + 1023) / 1024;

    // Launch order engineered so ncu (-s window) captures k_deg (4th kernel).
    k_init<<<nblkN, 256>>>();                                       // 1
    k_gbounds<<<nblkN, 256>>>(batch);                               // 2
    // GEMM1 first: G1 = X @ W1 (fp16 out) — CSR-independent
    k_gemmF<256, 40, 1, 0><<<dim3((NN + 255) / 256, 1), 160>>>(x, W1, nullptr, pG1h, NN, FA, FA);  // 3
    k_deg<<<nblkE, 256>>>(ei, ew);                                  // 4  <- PROFILED
    k_scan1<<<nblkSc, 1024>>>();                                    // 5
    k_scan3<<<nblkSc, 1024>>>();                                    // 6
    k_fill<<<nblkE, 256>>>(ei, ew);                                 // 7

    // Layer 1: H1 = relu(Â G1 + b1)   (fp16 gather -> fp16 out)
    k_agg<FA, 1><<<(NN + 7) / 8, 256>>>(pG1h, b1, pH1h);
    // Layer 2: T = Â H1; H2 = relu(T @ W2 + b2) (fp16 out)
    k_agg<FA, 0><<<(NN + 7) / 8, 256>>>(pH1h, nullptr, pT);
    k_gemmF<128, 80, 1, 1><<<dim3((NN + 127) / 128, 1), 160>>>(pT, W2, b2, pH2h, NN, FA, FB);
    // Layer 3: T = Â H2; H3 = relu(T @ W3 + b3) (fp32 out)
    k_agg<FB, 0><<<(NN + 7) / 8, 256>>>(pH2h, nullptr, pT);
    k_gemmF<128, 128, 0, 1><<<dim3((NN + 127) / 128, 1), 256>>>(pT, W3, b3, pH3, NN, FB, FC);

    // Pool -> FC1 -> FC2 + softmax
    k_pool<<<NG, dim3(FC, 4)>>>(pH3);
    k_gemmF<128, 128, 0, 1><<<dim3(4, 4), 256>>>(pPool, Wfc1, bfc1, pFc1, NG, FC, FH);
    k_fc2<<<(NG + 7) / 8, 256>>>(Wfc2, bfc2, out);
}

// round 13
// speedup vs baseline: 1.1271x; 1.1271x over previous
#include <cuda_runtime.h>
#include <cuda_bf16.h>
#include <cuda_fp16.h>
#include <math.h>

#define NN 100000
#define NE 1600000
#define NG 512
#define FA 40
#define FB 80
#define FC 128
#define FH 512   // fc1 hidden

typedef unsigned long long ULL;

// ---------------- f32x2 helpers (Blackwell dual-FP32 pipe) ----------------
__device__ __forceinline__ void fma2(ULL &d, ULL a, ULL b) {
    asm("fma.rn.f32x2 %0, %1, %2, %0;" : "+l"(d) : "l"(a), "l"(b));
}
__device__ __forceinline__ ULL bcast2(float x) {
    ULL r; asm("mov.b64 %0, {%1, %1};" : "=l"(r) : "f"(x)); return r;
}
__device__ __forceinline__ float2 upk2(ULL v) {
    float2 f; asm("mov.b64 {%0, %1}, %2;" : "=f"(f.x), "=f"(f.y) : "l"(v)); return f;
}

// ---------------- static device scratch ----------------
__device__ float  g_dinv[NN];       // deg -> rsqrt(deg)
__device__ float  g_self[NN];       // dinv^2 (self-loop norm)
__device__ int    g_cnt[NN];
__device__ int    g_fill[NN];
__device__ int    g_rowptr[NN + 1];
__device__ int    g_bsum[128];
__device__ int    g_gstart[NG + 1];
__device__ ULL    g_epack[NE];      // low32 = src id, high32 = norm (float bits)
__device__ __half g_Xh[NN * FA];    // x in fp16 (gather operand)
__device__ __half g_H1h[NN * FA];   // H1 in fp16
__device__ __half g_H2h[NN * FB];   // H2 in fp16
__device__ float  g_H3[NN * FC];    // H3 fp32 (pool input)
__device__ float  g_T[NN * FB];     // aggregated features (GEMM input, fp32)
__device__ float  g_pool[NG * FC];
__device__ float  g_fc1[NG * FH];

// ---------------- init: x->half + counters + graph bounds, one pass ----------------
__global__ void k_init(const float* __restrict__ x, const int* __restrict__ batch) {
    int i = blockIdx.x * blockDim.x + threadIdx.x;
    if (i < NN * FA / 2) {
        float2 v = ((const float2*)x)[i];
        ((__half2*)g_Xh)[i] = __floats2half2_rn(v.x, v.y);
    }
    if (i < NN) {
        g_dinv[i] = 1.0f; g_cnt[i] = 0; g_fill[i] = 0;
        int b = batch[i];
        if (i == 0) {
            for (int g = 0; g <= b; g++) g_gstart[g] = 0;
        } else {
            int p = batch[i - 1];
            for (int g = p + 1; g <= b; g++) g_gstart[g] = i;
        }
        if (i == NN - 1) {
            for (int g = b + 1; g <= NG; g++) g_gstart[g] = NN;
        }
    }
}

// ---------------- degree + count (fire-and-forget -> REDG) ----------------
__global__ void k_deg(const int* __restrict__ ei, const float* __restrict__ ew) {
    int e = blockIdx.x * blockDim.x + threadIdx.x;
    if (e >= NE) return;
    int c = ei[NE + e];
    atomicAdd(&g_dinv[c], ew[e]);
    atomicAdd(&g_cnt[c], 1);
}

// ---------------- scan phase 1: block sums (+ dinv transform folded) ----------------
__global__ void k_scan1() {
    __shared__ int sh[1024];
    int i = blockIdx.x * 1024 + threadIdx.x;
    if (i < NN) {
        float r = rsqrtf(g_dinv[i]);   // deg >= 1 (self loop)
        g_dinv[i] = r;
        g_self[i] = r * r;
    }
    sh[threadIdx.x] = (i < NN) ? g_cnt[i] : 0;
    __syncthreads();
    for (int s = 512; s > 0; s >>= 1) {
        if (threadIdx.x < s) sh[threadIdx.x] += sh[threadIdx.x + s];
        __syncthreads();
    }
    if (threadIdx.x == 0) g_bsum[blockIdx.x] = sh[0];
}

// ---------------- scan phase 2: intra-block scan + inline lookback ----------------
__global__ void k_scan3() {
    __shared__ int sh[1024];
    __shared__ int pre[128];
    int tid = threadIdx.x;
    int i = blockIdx.x * 1024 + tid;
    int v = (i < NN) ? g_cnt[i] : 0;
    sh[tid] = v;
    if (tid < 128) pre[tid] = (tid < blockIdx.x) ? g_bsum[tid] : 0;
    __syncthreads();
    for (int off = 1; off < 1024; off <<= 1) {
        int t = (tid >= off) ? sh[tid - off] : 0;
        __syncthreads();
        sh[tid] += t;
        __syncthreads();
    }
    if (tid < 64) pre[tid] += pre[tid + 64];
    __syncthreads();
    if (tid < 32) {
        int p = pre[tid] + pre[tid + 32];
#pragma unroll
        for (int off = 16; off > 0; off >>= 1)
            p += __shfl_down_sync(0xFFFFFFFFu, p, off);
        if (tid == 0) pre[0] = p;
    }
    __syncthreads();
    if (i <= NN) g_rowptr[i] = pre[0] + sh[tid] - v;
}

// ---------------- edge fill (CSR by destination, packed meta) ----------------
__global__ void k_fill(const int* __restrict__ ei, const float* __restrict__ ew) {
    int e = blockIdx.x * blockDim.x + threadIdx.x;
    if (e >= NE) return;
    int r = ei[e];
    int c = ei[NE + e];
    int pos = g_rowptr[c] + atomicAdd(&g_fill[c], 1);
    float norm = g_dinv[r] * ew[e] * g_dinv[c];
    g_epack[pos] = (ULL)(unsigned)r | ((ULL)__float_as_uint(norm) << 32);
}

// ---------------- gather-aggregate (warp per dst node): T = Â H, fp16 in ----------------
// Cooperative chunked edge loading: 32 lanes load 32 epacks coalesced, then
// src/weight distributed via register shuffles. One L2 wait per 32 edges.
template<int F>
__global__ void k_agg(const __half* __restrict__ H, float* __restrict__ OUT) {
    int warp = threadIdx.x >> 5;
    int lane = threadIdx.x & 31;
    int n = blockIdx.x * (blockDim.x >> 5) + warp;
    if (n >= NN) return;
    constexpr int NH = F / 2;            // half2 per row: 20 / 40
    constexpr int J  = (NH + 31) / 32;   // 1 / 2
    float2 acc[J];
    float sn = g_self[n];
    const __half2* hn = (const __half2*)(H + (size_t)n * F);
#pragma unroll
    for (int j = 0; j < J; j++) {
        int c = lane + 32 * j;
        acc[j] = make_float2(0.f, 0.f);
        if (c < NH) {
            float2 v = __half22float2(hn[c]);
            acc[j].x = sn * v.x; acc[j].y = sn * v.y;
        }
    }
    int beg = g_rowptr[n], end = g_rowptr[n + 1];
    for (int base = beg; base < end; base += 32) {
        int rem = end - base;
        int cnt = rem < 32 ? rem : 32;
        unsigned lo = 0, hi = 0;
        if (lane < cnt) {
            ULL m = g_epack[base + lane];
            lo = (unsigned)m;
            hi = (unsigned)(m >> 32);
        }
        int t = 0;
        for (; t + 4 <= cnt; t += 4) {
            unsigned s0 = __shfl_sync(0xFFFFFFFFu, lo, t);
            unsigned s1 = __shfl_sync(0xFFFFFFFFu, lo, t + 1);
            unsigned s2 = __shfl_sync(0xFFFFFFFFu, lo, t + 2);
            unsigned s3 = __shfl_sync(0xFFFFFFFFu, lo, t + 3);
            float w0 = __uint_as_float(__shfl_sync(0xFFFFFFFFu, hi, t));
            float w1 = __uint_as_float(__shfl_sync(0xFFFFFFFFu, hi, t + 1));
            float w2 = __uint_as_float(__shfl_sync(0xFFFFFFFFu, hi, t + 2));
            float w3 = __uint_as_float(__shfl_sync(0xFFFFFFFFu, hi, t + 3));
            const __half2* h0 = (const __half2*)(H + (size_t)s0 * F);
            const __half2* h1 = (const __half2*)(H + (size_t)s1 * F);
            const __half2* h2 = (const __half2*)(H + (size_t)s2 * F);
            const __half2* h3 = (const __half2*)(H + (size_t)s3 * F);
#pragma unroll
            for (int j = 0; j < J; j++) {
                int c = lane + 32 * j;
                if (c < NH) {
                    float2 v0 = __half22float2(h0[c]);
                    float2 v1 = __half22float2(h1[c]);
                    float2 v2 = __half22float2(h2[c]);
                    float2 v3 = __half22float2(h3[c]);
                    acc[j].x += w0 * v0.x + w1 * v1.x + w2 * v2.x + w3 * v3.x;
                    acc[j].y += w0 * v0.y + w1 * v1.y + w2 * v2.y + w3 * v3.y;
                }
            }
        }
        for (; t < cnt; t++) {
            unsigned s = __shfl_sync(0xFFFFFFFFu, lo, t);
            float w = __uint_as_float(__shfl_sync(0xFFFFFFFFu, hi, t));
            const __half2* hp = (const __half2*)(H + (size_t)s * F);
#pragma unroll
            for (int j = 0; j < J; j++) {
                int c = lane + 32 * j;
                if (c < NH) {
                    float2 v = __half22float2(hp[c]);
                    acc[j].x += w * v.x;
                    acc[j].y += w * v.y;
                }
            }
        }
    }
    float2* op = (float2*)(OUT + (size_t)n * F);
#pragma unroll
    for (int j = 0; j < J; j++) {
        int c = lane + 32 * j;
        if (c < NH) op[c] = acc[j];
    }
}

// ---------------- f32x2 SGEMM: C = relu(A @ W + b), fp32 or fp16 output ----------------
template<int BM, int BN, int OUTH>
__global__ void k_gemmF(const float* __restrict__ A, const float* __restrict__ W,
                        const float* __restrict__ bias, void* __restrict__ C,
                        int N, int K, int M) {
    constexpr int BK = 8;
    constexpr int NT = (BM / 8) * (BN / 8);
    __shared__ __align__(16) float As[BK][BM];
    __shared__ __align__(16) float Ws[BK][BN];
    int tid = threadIdx.x;
    int tx = tid % (BN / 8);
    int ty = tid / (BN / 8);
    int rowBase = blockIdx.x * BM;
    int colBase = blockIdx.y * BN;

    ULL acc[8][4];
#pragma unroll
    for (int i = 0; i < 8; i++)
#pragma unroll
        for (int j = 0; j < 4; j++) acc[i][j] = 0ull;

    for (int kt = 0; kt < K; kt += BK) {
        for (int idx = tid; idx < BM * BK / 4; idx += NT) {
            int r = idx % BM;
            int kp = (idx / BM) * 4;
            int gr = rowBase + r;
            float4 v = make_float4(0.f, 0.f, 0.f, 0.f);
            if (gr < N) v = *(const float4*)(A + (size_t)gr * K + kt + kp);
            As[kp + 0][r] = v.x; As[kp + 1][r] = v.y;
            As[kp + 2][r] = v.z; As[kp + 3][r] = v.w;
        }
        for (int idx = tid; idx < BK * BN / 4; idx += NT) {
            int kk = idx / (BN / 4);
            int j = (idx % (BN / 4)) * 4;
            *(float4*)&Ws[kk][j] = *(const float4*)(W + (size_t)(kt + kk) * M + colBase + j);
        }
        __syncthreads();
#pragma unroll
        for (int kk = 0; kk < BK; kk++) {
            float4 a0 = *(float4*)&As[kk][ty * 4];
            float4 a1 = *(float4*)&As[kk][BM / 2 + ty * 4];
            ulonglong2 w01 = *(ulonglong2*)&Ws[kk][tx * 4];
            ulonglong2 w23 = *(ulonglong2*)&Ws[kk][BN / 2 + tx * 4];
            float av[8] = {a0.x, a0.y, a0.z, a0.w, a1.x, a1.y, a1.z, a1.w};
#pragma unroll
            for (int i = 0; i < 8; i++) {
                ULL ap = bcast2(av[i]);
                fma2(acc[i][0], ap, w01.x);
                fma2(acc[i][1], ap, w01.y);
                fma2(acc[i][2], ap, w23.x);
                fma2(acc[i][3], ap, w23.y);
            }
        }
        __syncthreads();
    }

    int c0 = colBase + tx * 4;
    int c1 = colBase + BN / 2 + tx * 4;
    float b0x = bias[c0], b0y = bias[c0 + 1], b0z = bias[c0 + 2], b0w = bias[c0 + 3];
    float b1x = bias[c1], b1y = bias[c1 + 1], b1z = bias[c1 + 2], b1w = bias[c1 + 3];
#pragma unroll
    for (int i = 0; i < 8; i++) {
        int gr = rowBase + ((i < 4) ? (ty * 4 + i) : (BM / 2 + ty * 4 + (i - 4)));
        if (gr >= N) continue;
        float2 p;
        if (OUTH) {
            __half* cp = (__half*)C + (size_t)gr * M;
            p = upk2(acc[i][0]);
            *(__half2*)(cp + c0)     = __floats2half2_rn(fmaxf(p.x + b0x, 0.f), fmaxf(p.y + b0y, 0.f));
            p = upk2(acc[i][1]);
            *(__half2*)(cp + c0 + 2) = __floats2half2_rn(fmaxf(p.x + b0z, 0.f), fmaxf(p.y + b0w, 0.f));
            p = upk2(acc[i][2]);
            *(__half2*)(cp + c1)     = __floats2half2_rn(fmaxf(p.x + b1x, 0.f), fmaxf(p.y + b1y, 0.f));
            p = upk2(acc[i][3]);
            *(__half2*)(cp + c1 + 2) = __floats2half2_rn(fmaxf(p.x + b1z, 0.f), fmaxf(p.y + b1w, 0.f));
        } else {
            float* cp = (float*)C + (size_t)gr * M;
            p = upk2(acc[i][0]);
            *(float2*)(cp + c0)     = make_float2(fmaxf(p.x + b0x, 0.f), fmaxf(p.y + b0y, 0.f));
            p = upk2(acc[i][1]);
            *(float2*)(cp + c0 + 2) = make_float2(fmaxf(p.x + b0z, 0.f), fmaxf(p.y + b0w, 0.f));
            p = upk2(acc[i][2]);
            *(float2*)(cp + c1)     = make_float2(fmaxf(p.x + b1x, 0.f), fmaxf(p.y + b1y, 0.f));
            p = upk2(acc[i][3]);
            *(float2*)(cp + c1 + 2) = make_float2(fmaxf(p.x + b1z, 0.f), fmaxf(p.y + b1w, 0.f));
        }
    }
}

// ---------------- segmented global max pool (4 row-parallel lanes) ----------------
__global__ void k_pool(const float* __restrict__ H3) {
    __shared__ float red[4][FC];
    int g = blockIdx.x;
    int c = threadIdx.x;
    int ry = threadIdx.y;
    int beg = g_gstart[g], end = g_gstart[g + 1];
    float m = 0.f;                // H3 is post-relu (>= 0)
    for (int n = beg + ry; n < end; n += 4)
        m = fmaxf(m, H3[(size_t)n * FC + c]);
    red[ry][c] = m;
    __syncthreads();
    if (ry == 0) {
        m = fmaxf(fmaxf(red[0][c], red[1][c]), fmaxf(red[2][c], red[3][c]));
        g_pool[g * FC + c] = m;
    }
}

// ---------------- fc2 + softmax ----------------
__global__ void k_fc2(const float* __restrict__ Wfc2, const float* __restrict__ bfc2,
                      float* __restrict__ out) {
    int warp = threadIdx.x >> 5;
    int lane = threadIdx.x & 31;
    int g = blockIdx.x * (blockDim.x >> 5) + warp;
    if (g >= NG) return;
    float s0 = 0.f, s1 = 0.f;
    for (int k = lane; k < FH; k += 32) {
        float v = g_fc1[g * FH + k];
        s0 += v * Wfc2[k * 2 + 0];
        s1 += v * Wfc2[k * 2 + 1];
    }
#pragma unroll
    for (int off = 16; off > 0; off >>= 1) {
        s0 += __shfl_down_sync(0xFFFFFFFFu, s0, off);
        s1 += __shfl_down_sync(0xFFFFFFFFu, s1, off);
    }
    if (lane == 0) {
        s0 += bfc2[0]; s1 += bfc2[1];
        float m = fmaxf(s0, s1);
        float e0 = expf(s0 - m), e1 = expf(s1 - m);
        float inv = 1.f / (e0 + e1);
        out[g * 2 + 0] = e0 * inv;
        out[g * 2 + 1] = e1 * inv;
    }
}

// ---------------- host launch ----------------
extern "C" void kernel_launch(void* const* d_in, const int* in_sizes, int n_in,
                              void* d_out, int out_size) {
    const float* x     = (const float*)d_in[0];
    const int*   ei    = (const int*)  d_in[1];
    const float* ew    = (const float*)d_in[2];
    const int*   batch = (const int*)  d_in[3];
    const float* W1    = (const float*)d_in[4];
    const float* b1    = (const float*)d_in[5];
    const float* W2    = (const float*)d_in[6];
    const float* b2    = (const float*)d_in[7];
    const float* W3    = (const float*)d_in[8];
    const float* b3    = (const float*)d_in[9];
    const float* Wfc1  = (const float*)d_in[10];
    const float* bfc1  = (const float*)d_in[11];
    const float* Wfc2  = (const float*)d_in[12];
    const float* bfc2  = (const float*)d_in[13];
    float* out = (float*)d_out;

    __half *pXh, *pH1h, *pH2h;
    float *pH3, *pT, *pPool, *pFc1;
    cudaGetSymbolAddress((void**)&pXh,   g_Xh);
    cudaGetSymbolAddress((void**)&pH1h,  g_H1h);
    cudaGetSymbolAddress((void**)&pH2h,  g_H2h);
    cudaGetSymbolAddress((void**)&pH3,   g_H3);
    cudaGetSymbolAddress((void**)&pT,    g_T);
    cudaGetSymbolAddress((void**)&pPool, g_pool);
    cudaGetSymbolAddress((void**)&pFc1,  g_fc1);

    int nblkE  = (NE + 255) / 256;
    int nblkSc = (NN + 1023) / 1024;

    k_init<<<(NN * FA / 2 + 255) / 256, 256>>>(x, batch);
    k_deg<<<nblkE, 256>>>(ei, ew);
    k_scan1<<<nblkSc, 1024>>>();
    k_scan3<<<nblkSc, 1024>>>();
    k_fill<<<nblkE, 256>>>(ei, ew);

    // Layer 1: T = Â x;  H1 = relu(T @ W1 + b1)  -> fp16 H1
    k_agg<FA><<<(NN + 7) / 8, 256>>>(pXh, pT);
    k_gemmF<256, 40, 1><<<dim3((NN + 255) / 256, 1), 160>>>(pT, W1, b1, pH1h, NN, FA, FA);

    // Layer 2: T = Â H1; H2 = relu(T @ W2 + b2)  -> fp16 H2
    k_agg<FA><<<(NN + 7) / 8, 256>>>(pH1h, pT);
    k_gemmF<128, 80, 1><<<dim3((NN + 127) / 128, 1), 160>>>(pT, W2, b2, pH2h, NN, FA, FB);

    // Layer 3: T = Â H2; H3 = relu(T @ W3 + b3)  -> fp32 H3
    k_agg<FB><<<(NN + 7) / 8, 256>>>(pH2h, pT);
    k_gemmF<128, 128, 0><<<dim3((NN + 127) / 128, 1), 256>>>(pT, W3, b3, pH3, NN, FB, FC);

    // Pool -> FC1 -> FC2 + softmax
    k_pool<<<NG, dim3(FC, 4)>>>(pH3);
    k_gemmF<128, 128, 0><<<dim3(4, 4), 256>>>(pPool, Wfc1, bfc1, pFc1, NG, FC, FH);
    k_fc2<<<(NG + 7) / 8, 256>>>(Wfc2, bfc2, out);
}

// round 14
// speedup vs baseline: 1.1441x; 1.0151x over previous
#include <cuda_runtime.h>
#include <cuda_bf16.h>
#include <cuda_fp16.h>
#include <math.h>

#define NN 100000
#define NE 1600000
#define NG 512
#define FA 40
#define FB 80
#define FC 128
#define FH 512   // fc1 hidden

typedef unsigned long long ULL;

// ---------------- f32x2 helpers (Blackwell dual-FP32 pipe) ----------------
__device__ __forceinline__ void fma2(ULL &d, ULL a, ULL b) {
    asm("fma.rn.f32x2 %0, %1, %2, %0;" : "+l"(d) : "l"(a), "l"(b));
}
__device__ __forceinline__ ULL bcast2(float x) {
    ULL r; asm("mov.b64 %0, {%1, %1};" : "=l"(r) : "f"(x)); return r;
}
__device__ __forceinline__ float2 upk2(ULL v) {
    float2 f; asm("mov.b64 {%0, %1}, %2;" : "=f"(f.x), "=f"(f.y) : "l"(v)); return f;
}

// ---------------- static device scratch ----------------
__device__ float        g_dinv[NN];    // memset 0; deg sums edge weights; -> rsqrt(1+s)
__device__ float        g_self[NN];
__device__ int          g_cnt[NN];     // memset 0
__device__ int          g_fill[NN];    // memset 0
__device__ int          g_rowptr[NN + 1];
__device__ volatile ULL g_bpack[128];  // memset 0; bit62 = ready flag, low32 = block total
__device__ int          g_gstart[NG + 1];
__device__ ULL          g_epack[NE];   // low32 = src id, high32 = norm (float bits)
__device__ __half       g_H1h[NN * FA];
__device__ __half       g_H2h[NN * FB];
__device__ float        g_H3[NN * FC];
__device__ float        g_T[NN * FB];  // aggregated features (fp32 GEMM input)

// ---------------- degree + count (fire-and-forget -> REDG) ----------------
__global__ void k_deg(const int* __restrict__ ei, const float* __restrict__ ew) {
    int e = blockIdx.x * blockDim.x + threadIdx.x;
    if (e >= NE) return;
    int c = ei[NE + e];
    atomicAdd(&g_dinv[c], ew[e]);
    atomicAdd(&g_cnt[c], 1);
}

// ---------------- fused single-kernel scan (decoupled lookback) ----------------
// All 98 blocks resident in wave 1 (1024 thr, 148 SMs) -> lookback is deadlock-free.
__global__ void k_scanF() {
    __shared__ int sh[1024];
    __shared__ int blkpre;
    int tid = threadIdx.x, bx = blockIdx.x;
    int i = bx * 1024 + tid;
    int v = 0;
    if (i < NN) {
        float s = g_dinv[i];
        float r = rsqrtf(1.0f + s);    // +1 = self loop weight
        g_dinv[i] = r;
        g_self[i] = r * r;
        v = g_cnt[i];
    }
    sh[tid] = v;
    __syncthreads();
    for (int off = 1; off < 1024; off <<= 1) {
        int t = (tid >= off) ? sh[tid - off] : 0;
        __syncthreads();
        sh[tid] += t;
        __syncthreads();
    }
    // publish this block's total (single packed word: no fence needed)
    if (tid == 1023)
        g_bpack[bx] = (ULL)(unsigned)sh[1023] | (1ULL << 62);
    // lookback over preceding blocks (warp 0)
    if (tid < 32) {
        int acc = 0;
        for (int b = tid; b < bx; b += 32) {
            ULL p;
            do { p = g_bpack[b]; } while (!(p >> 62));
            acc += (int)(unsigned)p;
        }
#pragma unroll
        for (int off = 16; off > 0; off >>= 1)
            acc += __shfl_down_sync(0xFFFFFFFFu, acc, off);
        if (tid == 0) blkpre = acc;
    }
    __syncthreads();
    if (i <= NN) g_rowptr[i] = blkpre + sh[tid] - v;   // exclusive
}

// ---------------- edge fill (CSR by destination, packed meta) ----------------
__global__ void k_fill(const int* __restrict__ ei, const float* __restrict__ ew) {
    int e = blockIdx.x * blockDim.x + threadIdx.x;
    if (e >= NE) return;
    int r = ei[e];
    int c = ei[NE + e];
    int pos = g_rowptr[c] + atomicAdd(&g_fill[c], 1);
    float norm = g_dinv[r] * ew[e] * g_dinv[c];
    g_epack[pos] = (ULL)(unsigned)r | ((ULL)__float_as_uint(norm) << 32);
}

// ---------------- graph segment boundaries (batch sorted) ----------------
__global__ void k_gbounds(const int* __restrict__ batch) {
    int i = blockIdx.x * blockDim.x + threadIdx.x;
    if (i >= NN) return;
    int b = batch[i];
    if (i == 0) {
        for (int g = 0; g <= b; g++) g_gstart[g] = 0;
    } else {
        int p = batch[i - 1];
        for (int g = p + 1; g <= b; g++) g_gstart[g] = i;
    }
    if (i == NN - 1) {
        for (int g = b + 1; g <= NG; g++) g_gstart[g] = NN;
    }
}

// ---------------- gather-aggregate (warp per dst node): T = Â H ----------------
// HALF=1: H is fp16; HALF=0: H is fp32. Chunked cooperative edge loads + shfl.
template<int F, int HALF>
__global__ void k_agg(const void* __restrict__ Hv, float* __restrict__ OUT) {
    int warp = threadIdx.x >> 5;
    int lane = threadIdx.x & 31;
    int n = blockIdx.x * (blockDim.x >> 5) + warp;
    if (n >= NN) return;
    constexpr int NH = F / 2;            // pairs per row: 20 / 40
    constexpr int J  = (NH + 31) / 32;   // 1 / 2
    const __half* Hh = (const __half*)Hv;
    const float*  Hf = (const float*)Hv;
    float2 acc[J];
    float sn = g_self[n];
#pragma unroll
    for (int j = 0; j < J; j++) {
        int c = lane + 32 * j;
        acc[j] = make_float2(0.f, 0.f);
        if (c < NH) {
            float2 v;
            if (HALF) v = __half22float2(((const __half2*)(Hh + (size_t)n * F))[c]);
            else      v = ((const float2*)(Hf + (size_t)n * F))[c];
            acc[j].x = sn * v.x; acc[j].y = sn * v.y;
        }
    }
    int beg = g_rowptr[n], end = g_rowptr[n + 1];
    for (int base = beg; base < end; base += 32) {
        int rem = end - base;
        int cnt = rem < 32 ? rem : 32;
        unsigned lo = 0, hi = 0;
        if (lane < cnt) {
            ULL m = g_epack[base + lane];
            lo = (unsigned)m;
            hi = (unsigned)(m >> 32);
        }
        int t = 0;
        for (; t + 4 <= cnt; t += 4) {
            unsigned s0 = __shfl_sync(0xFFFFFFFFu, lo, t);
            unsigned s1 = __shfl_sync(0xFFFFFFFFu, lo, t + 1);
            unsigned s2 = __shfl_sync(0xFFFFFFFFu, lo, t + 2);
            unsigned s3 = __shfl_sync(0xFFFFFFFFu, lo, t + 3);
            float w0 = __uint_as_float(__shfl_sync(0xFFFFFFFFu, hi, t));
            float w1 = __uint_as_float(__shfl_sync(0xFFFFFFFFu, hi, t + 1));
            float w2 = __uint_as_float(__shfl_sync(0xFFFFFFFFu, hi, t + 2));
            float w3 = __uint_as_float(__shfl_sync(0xFFFFFFFFu, hi, t + 3));
#pragma unroll
            for (int j = 0; j < J; j++) {
                int c = lane + 32 * j;
                if (c < NH) {
                    float2 v0, v1, v2, v3;
                    if (HALF) {
                        v0 = __half22float2(((const __half2*)(Hh + (size_t)s0 * F))[c]);
                        v1 = __half22float2(((const __half2*)(Hh + (size_t)s1 * F))[c]);
                        v2 = __half22float2(((const __half2*)(Hh + (size_t)s2 * F))[c]);
                        v3 = __half22float2(((const __half2*)(Hh + (size_t)s3 * F))[c]);
                    } else {
                        v0 = ((const float2*)(Hf + (size_t)s0 * F))[c];
                        v1 = ((const float2*)(Hf + (size_t)s1 * F))[c];
                        v2 = ((const float2*)(Hf + (size_t)s2 * F))[c];
                        v3 = ((const float2*)(Hf + (size_t)s3 * F))[c];
                    }
                    acc[j].x += w0 * v0.x + w1 * v1.x + w2 * v2.x + w3 * v3.x;
                    acc[j].y += w0 * v0.y + w1 * v1.y + w2 * v2.y + w3 * v3.y;
                }
            }
        }
        for (; t < cnt; t++) {
            unsigned s = __shfl_sync(0xFFFFFFFFu, lo, t);
            float w = __uint_as_float(__shfl_sync(0xFFFFFFFFu, hi, t));
#pragma unroll
            for (int j = 0; j < J; j++) {
                int c = lane + 32 * j;
                if (c < NH) {
                    float2 v;
                    if (HALF) v = __half22float2(((const __half2*)(Hh + (size_t)s * F))[c]);
                    else      v = ((const float2*)(Hf + (size_t)s * F))[c];
                    acc[j].x += w * v.x;
                    acc[j].y += w * v.y;
                }
            }
        }
    }
    float2* op = (float2*)(OUT + (size_t)n * F);
#pragma unroll
    for (int j = 0; j < J; j++) {
        int c = lane + 32 * j;
        if (c < NH) op[c] = acc[j];
    }
}

// ---------------- f32x2 SGEMM: C = relu(A @ W + b), fp32 or fp16 output ----------------
template<int BM, int BN, int OUTH>
__global__ void k_gemmF(const float* __restrict__ A, const float* __restrict__ W,
                        const float* __restrict__ bias, void* __restrict__ C,
                        int N, int K, int M) {
    constexpr int BK = 8;
    constexpr int NT = (BM / 8) * (BN / 8);
    __shared__ __align__(16) float As[BK][BM];
    __shared__ __align__(16) float Ws[BK][BN];
    int tid = threadIdx.x;
    int tx = tid % (BN / 8);
    int ty = tid / (BN / 8);
    int rowBase = blockIdx.x * BM;
    int colBase = blockIdx.y * BN;

    ULL acc[8][4];
#pragma unroll
    for (int i = 0; i < 8; i++)
#pragma unroll
        for (int j = 0; j < 4; j++) acc[i][j] = 0ull;

    for (int kt = 0; kt < K; kt += BK) {
        for (int idx = tid; idx < BM * BK / 4; idx += NT) {
            int r = idx % BM;
            int kp = (idx / BM) * 4;
            int gr = rowBase + r;
            float4 v = make_float4(0.f, 0.f, 0.f, 0.f);
            if (gr < N) v = *(const float4*)(A + (size_t)gr * K + kt + kp);
            As[kp + 0][r] = v.x; As[kp + 1][r] = v.y;
            As[kp + 2][r] = v.z; As[kp + 3][r] = v.w;
        }
        for (int idx = tid; idx < BK * BN / 4; idx += NT) {
            int kk = idx / (BN / 4);
            int j = (idx % (BN / 4)) * 4;
            *(float4*)&Ws[kk][j] = *(const float4*)(W + (size_t)(kt + kk) * M + colBase + j);
        }
        __syncthreads();
#pragma unroll
        for (int kk = 0; kk < BK; kk++) {
            float4 a0 = *(float4*)&As[kk][ty * 4];
            float4 a1 = *(float4*)&As[kk][BM / 2 + ty * 4];
            ulonglong2 w01 = *(ulonglong2*)&Ws[kk][tx * 4];
            ulonglong2 w23 = *(ulonglong2*)&Ws[kk][BN / 2 + tx * 4];
            float av[8] = {a0.x, a0.y, a0.z, a0.w, a1.x, a1.y, a1.z, a1.w};
#pragma unroll
            for (int i = 0; i < 8; i++) {
                ULL ap = bcast2(av[i]);
                fma2(acc[i][0], ap, w01.x);
                fma2(acc[i][1], ap, w01.y);
                fma2(acc[i][2], ap, w23.x);
                fma2(acc[i][3], ap, w23.y);
            }
        }
        __syncthreads();
    }

    int c0 = colBase + tx * 4;
    int c1 = colBase + BN / 2 + tx * 4;
    float b0x = bias[c0], b0y = bias[c0 + 1], b0z = bias[c0 + 2], b0w = bias[c0 + 3];
    float b1x = bias[c1], b1y = bias[c1 + 1], b1z = bias[c1 + 2], b1w = bias[c1 + 3];
#pragma unroll
    for (int i = 0; i < 8; i++) {
        int gr = rowBase + ((i < 4) ? (ty * 4 + i) : (BM / 2 + ty * 4 + (i - 4)));
        if (gr >= N) continue;
        float2 p;
        if (OUTH) {
            __half* cp = (__half*)C + (size_t)gr * M;
            p = upk2(acc[i][0]);
            *(__half2*)(cp + c0)     = __floats2half2_rn(fmaxf(p.x + b0x, 0.f), fmaxf(p.y + b0y, 0.f));
            p = upk2(acc[i][1]);
            *(__half2*)(cp + c0 + 2) = __floats2half2_rn(fmaxf(p.x + b0z, 0.f), fmaxf(p.y + b0w, 0.f));
            p = upk2(acc[i][2]);
            *(__half2*)(cp + c1)     = __floats2half2_rn(fmaxf(p.x + b1x, 0.f), fmaxf(p.y + b1y, 0.f));
            p = upk2(acc[i][3]);
            *(__half2*)(cp + c1 + 2) = __floats2half2_rn(fmaxf(p.x + b1z, 0.f), fmaxf(p.y + b1w, 0.f));
        } else {
            float* cp = (float*)C + (size_t)gr * M;
            p = upk2(acc[i][0]);
            *(float2*)(cp + c0)     = make_float2(fmaxf(p.x + b0x, 0.f), fmaxf(p.y + b0y, 0.f));
            p = upk2(acc[i][1]);
            *(float2*)(cp + c0 + 2) = make_float2(fmaxf(p.x + b0z, 0.f), fmaxf(p.y + b0w, 0.f));
            p = upk2(acc[i][2]);
            *(float2*)(cp + c1)     = make_float2(fmaxf(p.x + b1x, 0.f), fmaxf(p.y + b1y, 0.f));
            p = upk2(acc[i][3]);
            *(float2*)(cp + c1 + 2) = make_float2(fmaxf(p.x + b1z, 0.f), fmaxf(p.y + b1w, 0.f));
        }
    }
}

// ---------------- fused pool + fc1 + fc2 + softmax (block per graph) ----------------
__global__ void k_poolfc(const float* __restrict__ H3,
                         const float* __restrict__ Wfc1, const float* __restrict__ bfc1,
                         const float* __restrict__ Wfc2, const float* __restrict__ bfc2,
                         float* __restrict__ out) {
    __shared__ float red[4][FC];
    __shared__ float pool_s[FC];
    __shared__ float fc1_s[FH];
    int g = blockIdx.x;
    int tid = threadIdx.x;             // 512
    int c = tid & 127, ry = tid >> 7;
    int beg = g_gstart[g], end = g_gstart[g + 1];
    float m = 0.f;                     // H3 post-relu (>= 0)
    for (int n = beg + ry; n < end; n += 4)
        m = fmaxf(m, H3[(size_t)n * FC + c]);
    red[ry][c] = m;
    __syncthreads();
    if (ry == 0)
        pool_s[c] = fmaxf(fmaxf(red[0][c], red[1][c]), fmaxf(red[2][c], red[3][c]));
    __syncthreads();
    // fc1: thread j computes output column j
    float acc = bfc1[tid];
#pragma unroll 4
    for (int k = 0; k < FC; k++)
        acc += pool_s[k] * Wfc1[k * FH + tid];
    fc1_s[tid] = fmaxf(acc, 0.f);
    __syncthreads();
    // fc2 + softmax (warp 0)
    if (tid < 32) {
        float s0 = 0.f, s1 = 0.f;
        for (int k = tid; k < FH; k += 32) {
            float v = fc1_s[k];
            s0 += v * Wfc2[k * 2 + 0];
            s1 += v * Wfc2[k * 2 + 1];
        }
#pragma unroll
        for (int off = 16; off > 0; off >>= 1) {
            s0 += __shfl_down_sync(0xFFFFFFFFu, s0, off);
            s1 += __shfl_down_sync(0xFFFFFFFFu, s1, off);
        }
        if (tid == 0) {
            s0 += bfc2[0]; s1 += bfc2[1];
            float mm = fmaxf(s0, s1);
            float e0 = expf(s0 - mm), e1 = expf(s1 - mm);
            float inv = 1.f / (e0 + e1);
            out[g * 2 + 0] = e0 * inv;
            out[g * 2 + 1] = e1 * inv;
        }
    }
}

// ---------------- host launch ----------------
extern "C" void kernel_launch(void* const* d_in, const int* in_sizes, int n_in,
                              void* d_out, int out_size) {
    const float* x     = (const float*)d_in[0];
    const int*   ei    = (const int*)  d_in[1];
    const float* ew    = (const float*)d_in[2];
    const int*   batch = (const int*)  d_in[3];
    const float* W1    = (const float*)d_in[4];
    const float* b1    = (const float*)d_in[5];
    const float* W2    = (const float*)d_in[6];
    const float* b2    = (const float*)d_in[7];
    const float* W3    = (const float*)d_in[8];
    const float* b3    = (const float*)d_in[9];
    const float* Wfc1  = (const float*)d_in[10];
    const float* bfc1  = (const float*)d_in[11];
    const float* Wfc2  = (const float*)d_in[12];
    const float* bfc2  = (const float*)d_in[13];
    float* out = (float*)d_out;

    __half *pH1h, *pH2h;
    float *pH3, *pT;
    void *pDinv, *pCnt, *pFill, *pBpack;
    cudaGetSymbolAddress((void**)&pH1h,  g_H1h);
    cudaGetSymbolAddress((void**)&pH2h,  g_H2h);
    cudaGetSymbolAddress((void**)&pH3,   g_H3);
    cudaGetSymbolAddress((void**)&pT,    g_T);
    cudaGetSymbolAddress(&pDinv,  g_dinv);
    cudaGetSymbolAddress(&pCnt,   g_cnt);
    cudaGetSymbolAddress(&pFill,  g_fill);
    cudaGetSymbolAddress(&pBpack, (const void*)g_bpack);

    int nblkN = (NN + 255) / 256;
    int nblkE = (NE + 255) / 256;

    cudaMemsetAsync(pDinv,  0, NN * sizeof(float));
    cudaMemsetAsync(pCnt,   0, NN * sizeof(int));
    cudaMemsetAsync(pFill,  0, NN * sizeof(int));
    cudaMemsetAsync(pBpack, 0, 128 * sizeof(ULL));

    k_deg<<<nblkE, 256>>>(ei, ew);                                   // 1
    k_scanF<<<(NN + 1023) / 1024, 1024>>>();                         // 2
    k_fill<<<nblkE, 256>>>(ei, ew);                                  // 3
    // Layer 1: T = Â x (fp32 gather)                                // 4 <- PROFILED
    k_agg<FA, 0><<<(NN + 7) / 8, 256>>>(x, pT);
    k_gbounds<<<nblkN, 256>>>(batch);                                // 5
    k_gemmF<256, 40, 1><<<dim3((NN + 255) / 256, 1), 160>>>(pT, W1, b1, pH1h, NN, FA, FA);   // 6

    // Layer 2
    k_agg<FA, 1><<<(NN + 7) / 8, 256>>>(pH1h, pT);                   // 7
    k_gemmF<128, 80, 1><<<dim3((NN + 127) / 128, 1), 160>>>(pT, W2, b2, pH2h, NN, FA, FB);   // 8

    // Layer 3
    k_agg<FB, 1><<<(NN + 7) / 8, 256>>>(pH2h, pT);                   // 9
    k_gemmF<128, 128, 0><<<dim3((NN + 127) / 128, 1), 256>>>(pT, W3, b3, pH3, NN, FB, FC);   // 10

    // Fused tail: pool -> fc1 -> fc2 -> softmax
    k_poolfc<<<NG, FH>>>(pH3, Wfc1, bfc1, Wfc2, bfc2, out);          // 11
}